// round 2
// baseline (speedup 1.0000x reference)
#include <cuda_runtime.h>

// axon_layer: dual-exponential PSP scan, warp-parallel linear-recurrence form.
//   m_t = dm*m_{t-1} + x_t ; s_t = ds*s_{t-1} + x_t ; psp_t = (m_t - s_t)*v0
// One warp per row (T=400). Lane owns 8 contiguous elements; chunks [256, 144].
// Constant-decay linear scan: local serial scan + Kogge-Stone over lane tails
// with hop ratio d^8. No shared memory, no __syncthreads.
//
// Inputs: [0] input_spikes f32 [B,F,T]  [1] decay_m f32 [F]
//         [2] decay_s f32 [F]           [3] v_0 f32 scalar
// Output: psps [B,F,T] then m_T [B,F] then s_T [B,F].

#define AX_T 400
#define FULLM 0xffffffffu

// Per-lane constants for one recurrence with per-step decay d:
//   pw[j]   = d^(j+1), j=0..7
//   c[k]    = masked Kogge-Stone hop constant: (lane >= 2^k) ? (d^8)^(2^k) : 0
//   rlane   = (d^8)^lane   (carry multiplier across the warp)
__device__ __forceinline__ void ax_consts(float d, int lane,
                                          float pw[8], float c[5], float& rlane)
{
    pw[0] = d;
#pragma unroll
    for (int j = 1; j < 8; ++j) pw[j] = pw[j - 1] * d;
    float p1 = pw[7];            // d^8
    float p2 = p1 * p1;
    float p4 = p2 * p2;
    float p8 = p4 * p4;
    float p16 = p8 * p8;
    c[0] = (lane >= 1)  ? p1  : 0.f;
    c[1] = (lane >= 2)  ? p2  : 0.f;
    c[2] = (lane >= 4)  ? p4  : 0.f;
    c[3] = (lane >= 8)  ? p8  : 0.f;
    c[4] = (lane >= 16) ? p16 : 0.f;
    float rl = 1.f;
    if (lane & 1)  rl *= p1;
    if (lane & 2)  rl *= p2;
    if (lane & 4)  rl *= p4;
    if (lane & 8)  rl *= p8;
    if (lane & 16) rl *= p16;
    rlane = rl;
}

// Scan one chunk (8 elements/lane) of one recurrence. carry in/out is the
// recurrence state entering/leaving the chunk (broadcast across the warp).
__device__ __forceinline__ void ax_scan8(const float xv[8], const float pw[8],
                                         const float c[5], float rlane,
                                         float& carry, int lane, int last_lane,
                                         float mv[8])
{
    float l[8];
    l[0] = xv[0];
#pragma unroll
    for (int j = 1; j < 8; ++j) l[j] = fmaf(l[j - 1], pw[0], xv[j]);

    float S = l[7];
#pragma unroll
    for (int k = 0; k < 5; ++k) {
        float v = __shfl_up_sync(FULLM, S, 1 << k);
        S = fmaf(v, c[k], S);               // masked const -> no predication
    }
    float excl = __shfl_up_sync(FULLM, S, 1);
    if (lane == 0) excl = 0.f;
    float pref = fmaf(carry, rlane, excl);  // state entering this lane's segment
#pragma unroll
    for (int j = 0; j < 8; ++j) mv[j] = fmaf(pref, pw[j], l[j]);
    carry = __shfl_sync(FULLM, mv[7], last_lane);
}

__global__ void __launch_bounds__(256)
axon_scan_kernel(const float* __restrict__ x,
                 const float* __restrict__ decay_m,
                 const float* __restrict__ decay_s,
                 const float* __restrict__ v0p,
                 float* __restrict__ out,
                 int F, long long n_rows)
{
    const int lane = threadIdx.x & 31;
    const long long row = (long long)blockIdx.x * 8 + (threadIdx.x >> 5);

    const int f = (int)(row % F);
    const float dm = __ldg(&decay_m[f]);
    const float ds = __ldg(&decay_s[f]);
    const float v0 = __ldg(v0p);

    const float* __restrict__ rowp = x + row * AX_T;
    float* __restrict__ outp = out + row * AX_T;

    const bool tail_active = lane < 18;     // 144 tail elements = 18 lanes * 8

    // ---- all loads up front (MLP=4 per thread) ----
    float4 a0 = *(const float4*)(rowp + lane * 8);
    float4 a1 = *(const float4*)(rowp + lane * 8 + 4);
    float4 b0 = make_float4(0.f, 0.f, 0.f, 0.f);
    float4 b1 = make_float4(0.f, 0.f, 0.f, 0.f);
    if (tail_active) {
        b0 = *(const float4*)(rowp + 256 + lane * 8);
        b1 = *(const float4*)(rowp + 256 + lane * 8 + 4);
    }

    // ---- per-lane constants ----
    float pwm[8], cm[5], rml;
    float pws[8], cs[5], rsl;
    ax_consts(dm, lane, pwm, cm, rml);
    ax_consts(ds, lane, pws, cs, rsl);

    float carry_m = 0.f, carry_s = 0.f;

    // ---- chunk 0: elements [0, 256) ----
    {
        float xv[8] = {a0.x, a0.y, a0.z, a0.w, a1.x, a1.y, a1.z, a1.w};
        float mv[8], sv[8];
        ax_scan8(xv, pwm, cm, rml, carry_m, lane, 31, mv);
        ax_scan8(xv, pws, cs, rsl, carry_s, lane, 31, sv);
        float4 o0, o1;
        o0.x = (mv[0] - sv[0]) * v0;  o0.y = (mv[1] - sv[1]) * v0;
        o0.z = (mv[2] - sv[2]) * v0;  o0.w = (mv[3] - sv[3]) * v0;
        o1.x = (mv[4] - sv[4]) * v0;  o1.y = (mv[5] - sv[5]) * v0;
        o1.z = (mv[6] - sv[6]) * v0;  o1.w = (mv[7] - sv[7]) * v0;
        *(float4*)(outp + lane * 8)     = o0;
        *(float4*)(outp + lane * 8 + 4) = o1;
    }

    // ---- chunk 1 (tail): elements [256, 400), lanes 0..17 ----
    {
        float xv[8] = {b0.x, b0.y, b0.z, b0.w, b1.x, b1.y, b1.z, b1.w};
        float mv[8], sv[8];
        ax_scan8(xv, pwm, cm, rml, carry_m, lane, 17, mv);
        ax_scan8(xv, pws, cs, rsl, carry_s, lane, 17, sv);
        if (tail_active) {
            float4 o0, o1;
            o0.x = (mv[0] - sv[0]) * v0;  o0.y = (mv[1] - sv[1]) * v0;
            o0.z = (mv[2] - sv[2]) * v0;  o0.w = (mv[3] - sv[3]) * v0;
            o1.x = (mv[4] - sv[4]) * v0;  o1.y = (mv[5] - sv[5]) * v0;
            o1.z = (mv[6] - sv[6]) * v0;  o1.w = (mv[7] - sv[7]) * v0;
            *(float4*)(outp + 256 + lane * 8)     = o0;
            *(float4*)(outp + 256 + lane * 8 + 4) = o1;
        }
    }

    // ---- final states: carry_m/carry_s hold m_T, s_T (broadcast) ----
    if (lane == 0) {
        const long long psps = n_rows * AX_T;
        out[psps + row]          = carry_m;
        out[psps + n_rows + row] = carry_s;
    }
}

extern "C" void kernel_launch(void* const* d_in, const int* in_sizes, int n_in,
                              void* d_out, int out_size)
{
    const float* x   = (const float*)d_in[0];
    const float* dmv = (const float*)d_in[1];
    const float* dsv = (const float*)d_in[2];
    const float* v0p = (const float*)d_in[3];
    float* out = (float*)d_out;

    const int F = in_sizes[1];                       // 4096
    const long long total = (long long)in_sizes[0];  // B*F*T
    const long long n_rows = total / AX_T;           // B*F = 131072

    const int grid = (int)(n_rows / 8);              // 8 warps/block, 1 row/warp
    axon_scan_kernel<<<grid, 256>>>(x, dmv, dsv, v0p, out, F, n_rows);
}

// round 3
// speedup vs baseline: 1.0470x; 1.0470x over previous
#include <cuda_runtime.h>

// axon_layer: dual-exponential PSP scan.
//   m_t = m_{t-1}*dm + x_t ; s_t = s_{t-1}*ds + x_t ; psp_t = (m_t - s_t)*v0
// Thread-per-row sequential scan over smem-staged tiles, with a depth-2
// cp.async pipeline (loads for chunk i+1 in flight during compute/store of i).
//
// Inputs: [0] input_spikes f32 [B,F,T]  [1] decay_m f32 [F]
//         [2] decay_s f32 [F]           [3] v_0 f32 scalar
// Output: psps [B,F,T] then m_T [B,F] then s_T [B,F].

#define AX_THREADS 128
#define AX_ROWS    128
#define AX_T       400
#define AX_CH4     10            // float4 per chunk (40 floats)
#define AX_STRIDE  11            // padded row stride in float4 (odd -> no conflicts)
#define AX_NCHUNK  10
#define AX_RQ      (AX_T / 4)    // 100 float4 per full row

__device__ __forceinline__ void ax_cp_async16(void* smem_dst, const void* gmem_src) {
    unsigned saddr = (unsigned)__cvta_generic_to_shared(smem_dst);
    asm volatile("cp.async.cg.shared.global [%0], [%1], 16;\n"
                 :: "r"(saddr), "l"(gmem_src));
}
__device__ __forceinline__ void ax_cp_commit() {
    asm volatile("cp.async.commit_group;\n");
}
template <int N>
__device__ __forceinline__ void ax_cp_wait() {
    asm volatile("cp.async.wait_group %0;\n" :: "n"(N));
}

extern __shared__ float4 ax_smem[];   // 2 * AX_ROWS * AX_STRIDE float4 = 45056 B

__device__ __forceinline__ void ax_issue_chunk(const float4* __restrict__ gin,
                                               float4* __restrict__ buf,
                                               int ch, int tid)
{
#pragma unroll
    for (int i = 0; i < AX_CH4; ++i) {
        int idx = i * AX_THREADS + tid;          // 0..1279 linear over tile
        int r = idx / AX_CH4;
        int c = idx - r * AX_CH4;
        ax_cp_async16(&buf[r * AX_STRIDE + c],
                      &gin[(long long)r * AX_RQ + ch * AX_CH4 + c]);
    }
    ax_cp_commit();
}

__global__ void __launch_bounds__(AX_THREADS)
axon_pipe_kernel(const float* __restrict__ x,
                 const float* __restrict__ decay_m,
                 const float* __restrict__ decay_s,
                 const float* __restrict__ v0p,
                 float* __restrict__ out,
                 int F, long long n_rows)
{
    const int tid = threadIdx.x;
    const long long row0 = (long long)blockIdx.x * AX_ROWS;
    const long long my_row = row0 + tid;

    const float dm = __ldg(&decay_m[(int)(my_row % F)]);
    const float ds = __ldg(&decay_s[(int)(my_row % F)]);
    const float v0 = __ldg(v0p);

    float m = 0.0f, s = 0.0f;

    const float4* __restrict__ gin  = (const float4*)x + row0 * AX_RQ;
    float4* __restrict__       gout = (float4*)out     + row0 * AX_RQ;

    float4* buf0 = ax_smem;
    float4* buf1 = ax_smem + AX_ROWS * AX_STRIDE;

    // ---- prologue: chunks 0 and 1 in flight ----
    ax_issue_chunk(gin, buf0, 0, tid);
    ax_issue_chunk(gin, buf1, 1, tid);

    const int rbase = tid * AX_STRIDE;

    for (int ch = 0; ch < AX_NCHUNK; ++ch) {
        float4* buf = (ch & 1) ? buf1 : buf0;

        ax_cp_wait<1>();          // chunk ch resident; chunk ch+1 may still fly
        __syncthreads();

        // ---- sequential scan along T for this thread's row (in place) ----
#pragma unroll
        for (int t4 = 0; t4 < AX_CH4; ++t4) {
            float4 q = buf[rbase + t4];
            float4 o;
            m = fmaf(m, dm, q.x); s = fmaf(s, ds, q.x); o.x = (m - s) * v0;
            m = fmaf(m, dm, q.y); s = fmaf(s, ds, q.y); o.y = (m - s) * v0;
            m = fmaf(m, dm, q.z); s = fmaf(s, ds, q.z); o.z = (m - s) * v0;
            m = fmaf(m, dm, q.w); s = fmaf(s, ds, q.w); o.w = (m - s) * v0;
            buf[rbase + t4] = o;
        }
        __syncthreads();

        // ---- coalesced store of chunk ch ----
#pragma unroll
        for (int i = 0; i < AX_CH4; ++i) {
            int idx = i * AX_THREADS + tid;
            int r = idx / AX_CH4;
            int c = idx - r * AX_CH4;
            gout[(long long)r * AX_RQ + ch * AX_CH4 + c] = buf[r * AX_STRIDE + c];
        }
        __syncthreads();          // all smem reads done -> buffer reusable

        // ---- refill this buffer with chunk ch+2 ----
        if (ch + 2 < AX_NCHUNK) {
            ax_issue_chunk(gin, buf, ch + 2, tid);
        } else {
            ax_cp_commit();       // keep group counting uniform
        }
    }

    // ---- final states ----
    const long long psps = n_rows * AX_T;
    out[psps + my_row]          = m;
    out[psps + n_rows + my_row] = s;
}

extern "C" void kernel_launch(void* const* d_in, const int* in_sizes, int n_in,
                              void* d_out, int out_size)
{
    const float* x   = (const float*)d_in[0];
    const float* dmv = (const float*)d_in[1];
    const float* dsv = (const float*)d_in[2];
    const float* v0p = (const float*)d_in[3];
    float* out = (float*)d_out;

    const int F = in_sizes[1];                       // 4096
    const long long total = (long long)in_sizes[0];  // B*F*T
    const long long n_rows = total / AX_T;           // B*F = 131072
    const int grid = (int)(n_rows / AX_ROWS);        // 1024

    const int smem_bytes = 2 * AX_ROWS * AX_STRIDE * (int)sizeof(float4);

    static bool attr_set = false;
    if (!attr_set) {
        cudaFuncSetAttribute(axon_pipe_kernel,
                             cudaFuncAttributeMaxDynamicSharedMemorySize,
                             smem_bytes);
        attr_set = true;
    }

    axon_pipe_kernel<<<grid, AX_THREADS, smem_bytes>>>(
        x, dmv, dsv, v0p, out, F, n_rows);
}